// round 1
// baseline (speedup 1.0000x reference)
#include <cuda_runtime.h>

// Problem constants (match reference)
#define NB 16384      // B
#define NK 50         // K
#define NH 64         // H
#define REG 0.01

// Loss accumulators — device globals (no allocations allowed).
__device__ double g_mse;
__device__ double g_ue;
__device__ double g_ie;

__global__ void mf_zero_acc() {
    g_mse = 0.0; g_ue = 0.0; g_ie = 0.0;
}

__global__ __launch_bounds__(128, 8) void mf_main(
    const float* __restrict__ user_weight,   // [100000, 64]
    const float* __restrict__ item_weight,   // [1000000, 64]
    const float* __restrict__ user_bias,     // [100000, 1]
    const float* __restrict__ item_bias,     // [1000000, 1]
    const float* __restrict__ bias,          // [1]
    const float* __restrict__ target,        // [B, K]
    const int*   __restrict__ user,          // [B]
    const int*   __restrict__ item,          // [B, K]
    float* __restrict__ out)                 // [B*K + 1]
{
    const int b    = blockIdx.x;
    const int tid  = threadIdx.x;
    const int warp = tid >> 5;
    const int lane = tid & 31;

    // --- user embedding: ue = user_weight[u] + user_bias[u] (broadcast) ---
    const int u = user[b];
    const float ub = __ldg(user_bias + u);
    const float2 uw = __ldg((const float2*)(user_weight + (size_t)u * NH) + lane);
    const float uex = uw.x + ub;
    const float uey = uw.y + ub;

    const float bias0 = __ldg(bias);

    float mse_acc = 0.0f;   // valid on lane 0 of each warp
    float ie_acc  = 0.0f;

    // --- items: each warp handles k = warp, warp+4, ... ---
    for (int k = warp; k < NK; k += 4) {
        const int it = item[b * NK + k];
        const float ib = __ldg(item_bias + it);
        const float2 v = __ldg((const float2*)(item_weight + (size_t)it * NH) + lane);
        const float vx = v.x + ib;
        const float vy = v.y + ib;

        float d = uex * vx + uey * vy;       // dot(ue, ie) partial
        float s = vx * vx + vy * vy;         // ||ie||^2 partial

        #pragma unroll
        for (int o = 16; o > 0; o >>= 1) {
            d += __shfl_xor_sync(0xffffffffu, d, o);
            s += __shfl_xor_sync(0xffffffffu, s, o);
        }

        if (lane == 0) {
            const float pred = d + bias0;
            out[b * NK + k] = pred;
            const float diff = pred - target[b * NK + k];
            mse_acc += diff * diff;
            ie_acc  += sqrtf(s);
        }
    }

    // --- ||ue|| (warp 0 only; result lands on tid 0) ---
    float ue_norm = 0.0f;
    if (warp == 0) {
        float q = uex * uex + uey * uey;
        #pragma unroll
        for (int o = 16; o > 0; o >>= 1)
            q += __shfl_xor_sync(0xffffffffu, q, o);
        ue_norm = sqrtf(q);
    }

    // --- block reduce (4 warps) + single atomic per quantity ---
    __shared__ float s_mse[4];
    __shared__ float s_ie[4];
    if (lane == 0) { s_mse[warp] = mse_acc; s_ie[warp] = ie_acc; }
    __syncthreads();
    if (tid == 0) {
        const float m = s_mse[0] + s_mse[1] + s_mse[2] + s_mse[3];
        const float e = s_ie[0]  + s_ie[1]  + s_ie[2]  + s_ie[3];
        atomicAdd(&g_mse, (double)m);
        atomicAdd(&g_ie,  (double)e);
        atomicAdd(&g_ue,  (double)ue_norm);
    }
}

__global__ void mf_finalize(float* __restrict__ out) {
    const double n_bk = (double)NB * (double)NK;
    const double loss = g_mse / n_bk
                      + REG * (g_ue / (double)NB)
                      + REG * (g_ie / n_bk);
    out[NB * NK] = (float)loss;
}

extern "C" void kernel_launch(void* const* d_in, const int* in_sizes, int n_in,
                              void* d_out, int out_size) {
    const float* user_weight = (const float*)d_in[0];
    const float* item_weight = (const float*)d_in[1];
    const float* user_bias   = (const float*)d_in[2];
    const float* item_bias   = (const float*)d_in[3];
    const float* bias        = (const float*)d_in[4];
    const float* target      = (const float*)d_in[5];
    const int*   user        = (const int*)d_in[6];
    const int*   item        = (const int*)d_in[7];
    float* out = (float*)d_out;

    mf_zero_acc<<<1, 1>>>();
    mf_main<<<NB, 128>>>(user_weight, item_weight, user_bias, item_bias,
                         bias, target, user, item, out);
    mf_finalize<<<1, 1>>>(out);
}